// round 15
// baseline (speedup 1.0000x reference)
#include <cuda_runtime.h>
#include <cuda_fp16.h>
#include <math.h>
#include <stdint.h>

#define NN 8192
#define MM 8192
#define DD 512
#define YY 256

// Scratch (device globals -- no runtime allocation allowed)
// g_kmath is stored TILED: [tileN(64)][tileM(64)][128][128] halfs, 32KB/tile.
__device__ __half g_kmath[(size_t)NN * (size_t)MM];  // 128 MB
__device__ __half g_xh[(size_t)NN * DD];             // 8 MB
__device__ __half g_zh[(size_t)MM * DD];             // 8 MB
__device__ __half g_wth[(size_t)YY * MM];            // W^T, 4 MB
__device__ float g_xsq[NN];
__device__ float g_zsq[MM];

#define KTILE 16384   // halfs per 128x128 kmat tile

// ---------------------------------------------------------------------------
__device__ __forceinline__ uint32_t smem_to_u32(const void* p) {
    uint32_t a;
    asm("{ .reg .u64 t; cvta.to.shared.u64 t, %1; cvt.u32.u64 %0, t; }"
        : "=r"(a) : "l"(p));
    return a;
}

__device__ __forceinline__ void mma_f16(float* c, const uint32_t* a, const uint32_t* b) {
    asm volatile(
        "mma.sync.aligned.m16n8k16.row.col.f32.f16.f16.f32 "
        "{%0,%1,%2,%3}, {%4,%5,%6,%7}, {%8,%9}, {%0,%1,%2,%3};\n"
        : "+f"(c[0]), "+f"(c[1]), "+f"(c[2]), "+f"(c[3])
        : "r"(a[0]), "r"(a[1]), "r"(a[2]), "r"(a[3]), "r"(b[0]), "r"(b[1]));
}

__device__ __forceinline__ void ldsm_x4(uint32_t* r, uint32_t addr) {
    asm volatile("ldmatrix.sync.aligned.m8n8.x4.shared.b16 {%0,%1,%2,%3}, [%4];"
                 : "=r"(r[0]), "=r"(r[1]), "=r"(r[2]), "=r"(r[3]) : "r"(addr));
}

__device__ __forceinline__ void cpa16(uint32_t dst, const void* src) {
    asm volatile("cp.async.cg.shared.global [%0], [%1], 16;" :: "r"(dst), "l"(src));
}
#define CPA_COMMIT() asm volatile("cp.async.commit_group;" ::: "memory")
#define CPA_WAIT(n)  asm volatile("cp.async.wait_group %0;" :: "n"(n) : "memory")

__device__ __forceinline__ float sqrt_approx(float x) {
    float r;
    asm("sqrt.approx.f32 %0, %1;" : "=f"(r) : "f"(x));
    return r;
}

__device__ __forceinline__ void redadd(float* p, float v) {
    asm volatile("red.global.add.f32 [%0], %1;" :: "l"(p), "f"(v) : "memory");
}

// SW128 swizzle for BK=64 fp16 rows (128 B/row): conflict-free cp.async + ldmatrix
__device__ __forceinline__ uint32_t swz(int row, int colh) {
    return (uint32_t)(row * 128 + ((colh * 2) ^ ((row & 7) * 16)));
}

// padded layout stride (halfs) for G2
#define SPH 72
// G1 epilogue staging stride (halfs)
#define EPS 136

// ---------------------------------------------------------------------------
// prep: one pass over X and Z: emit fp16 copy + row squared norm.
// ---------------------------------------------------------------------------
__global__ void prep_kernel(const float* __restrict__ X, const float* __restrict__ Z,
                            __half* __restrict__ xh, __half* __restrict__ zh,
                            float* __restrict__ xsq, float* __restrict__ zsq) {
    int b = blockIdx.x;
    const float* src;  __half* dst;  float* nrm;  int row;
    if (b < NN) { src = X; dst = xh; nrm = xsq; row = b; }
    else        { src = Z; dst = zh; nrm = zsq; row = b - NN; }
    const int t = threadIdx.x;
    float4 v = reinterpret_cast<const float4*>(src + (size_t)row * DD)[t];
    float s = v.x * v.x + v.y * v.y + v.z * v.z + v.w * v.w;
    __half2 h0 = __floats2half2_rn(v.x, v.y);
    __half2 h1 = __floats2half2_rn(v.z, v.w);
    uint2 packed;
    packed.x = *reinterpret_cast<uint32_t*>(&h0);
    packed.y = *reinterpret_cast<uint32_t*>(&h1);
    reinterpret_cast<uint2*>(dst + (size_t)row * DD)[t] = packed;
#pragma unroll
    for (int o = 16; o; o >>= 1) s += __shfl_down_sync(0xffffffffu, s, o);
    __shared__ float red[4];
    if ((t & 31) == 0) red[t >> 5] = s;
    __syncthreads();
    if (t == 0) nrm[row] = red[0] + red[1] + red[2] + red[3];
}

// W [8192, 256] -> g_wth [256, 8192] fp16; also zeroes O (same geometry).
__global__ void wtrans_zero_kernel(const float* __restrict__ W, float4* __restrict__ O) {
    __shared__ float t[32][33];
    int kb = blockIdx.y * 32, yb = blockIdx.x * 32;
    int tx = threadIdx.x, ty = threadIdx.y;  // 32 x 8
    int flat = ty * 32 + tx;
    size_t bid = (size_t)blockIdx.y * gridDim.x + blockIdx.x;   // 0..2047
    O[bid * 256 + flat] = make_float4(0.f, 0.f, 0.f, 0.f);
#pragma unroll
    for (int r = 0; r < 4; ++r)
        t[ty + r * 8][tx] = W[(size_t)(kb + ty + r * 8) * YY + yb + tx];
    __syncthreads();
#pragma unroll
    for (int r = 0; r < 4; ++r)
        g_wth[(size_t)(yb + ty + r * 8) * MM + kb + tx] =
            __float2half_rn(t[tx][ty + r * 8]);
}

// ---------------------------------------------------------------------------
// G1: S = X Z^T (CTA 128x128, BK=64, 3-stage 1-sync cp.async, SW128 smem)
// smem: 3 x (A + B) 16KB tiles = 98304 B -> occ 2
// 8 warps = 2(M) x 4(N); warp tile 64x32
// Epilogue: laplacian -> smem stage -> ONE contiguous 32KB tile store.
// ---------------------------------------------------------------------------
#define TSW 16384

__global__ __launch_bounds__(256, 2) void kmat_h_kernel() {
    extern __shared__ __half smh[];
    const uint32_t smb = smem_to_u32(smh);

    const int tid  = threadIdx.x;
    const int lane = tid & 31;
    const int warp = tid >> 5;
    const int quad = lane >> 2;
    const int tig  = lane & 3;
    const int lj   = lane >> 3;
    const int lr   = lane & 7;
    const int warpM = warp & 1;
    const int warpN = warp >> 1;
    const int rowBase = blockIdx.y * 128;
    const int colBase = blockIdx.x * 128;

    const __half* Ap = g_xh + (size_t)rowBase * DD;
    const __half* Bp = g_zh + (size_t)colBase * DD;

    float acc[4][4][4];
#pragma unroll
    for (int i = 0; i < 4; ++i)
#pragma unroll
        for (int j = 0; j < 4; ++j)
#pragma unroll
            for (int e = 0; e < 4; ++e) acc[i][j][e] = 0.f;

    auto load_slab = [&](int buf, int s) {
        const int kt = s * 64;
        const uint32_t dA = smb + (uint32_t)buf * TSW;
        const uint32_t dB = smb + 3u * TSW + (uint32_t)buf * TSW;
#pragma unroll
        for (int u = 0; u < 4; ++u) {
            int idx = tid + u * 256;
            int r   = idx >> 3;
            int c8  = idx & 7;
            uint32_t so = swz(r, c8 * 8);
            cpa16(dA + so, Ap + (size_t)r * DD + kt + c8 * 8);
            cpa16(dB + so, Bp + (size_t)r * DD + kt + c8 * 8);
        }
        CPA_COMMIT();
    };

    auto compute = [&](int buf) {
        const uint32_t A = smb + (uint32_t)buf * TSW;
        const uint32_t B = smb + 3u * TSW + (uint32_t)buf * TSW;
#pragma unroll
        for (int kk = 0; kk < 64; kk += 16) {
            uint32_t afr[4][4], bfr[2][4];
#pragma unroll
            for (int mi = 0; mi < 4; ++mi) {
                int row = warpM * 64 + mi * 16 + (lj & 1) * 8 + lr;
                int col = kk + (lj >> 1) * 8;
                ldsm_x4(afr[mi], A + swz(row, col));
            }
#pragma unroll
            for (int np = 0; np < 2; ++np) {
                int row = warpN * 32 + np * 16 + (lj >> 1) * 8 + lr;
                int col = kk + (lj & 1) * 8;
                ldsm_x4(bfr[np], B + swz(row, col));
            }
#pragma unroll
            for (int mi = 0; mi < 4; ++mi)
#pragma unroll
                for (int np = 0; np < 2; ++np) {
                    mma_f16(acc[mi][np * 2 + 0], afr[mi], &bfr[np][0]);
                    mma_f16(acc[mi][np * 2 + 1], afr[mi], &bfr[np][2]);
                }
        }
    };

    const int S = DD / 64;  // 8
    load_slab(0, 0);
    load_slab(1, 1);
#pragma unroll 1
    for (int s = 0; s < S; ++s) {
        if (s + 1 < S) { CPA_WAIT(1); } else { CPA_WAIT(0); }
        __syncthreads();
        if (s + 2 < S) load_slab((s + 2) % 3, s + 2);
        compute(s % 3);
    }

    // Epilogue: laplacian -> fp16, staged through smem
    __syncthreads();
#pragma unroll
    for (int mi = 0; mi < 4; ++mi) {
        int rl0 = warpM * 64 + mi * 16 + quad;
        int rl1 = rl0 + 8;
        float xs0 = __ldg(&g_xsq[rowBase + rl0]);
        float xs1 = __ldg(&g_xsq[rowBase + rl1]);
#pragma unroll
        for (int ni = 0; ni < 4; ++ni) {
            int cl = warpN * 32 + ni * 8 + 2 * tig;
            float zs0 = __ldg(&g_zsq[colBase + cl]);
            float zs1 = __ldg(&g_zsq[colBase + cl + 1]);
            float v00 = __expf(-0.1f * sqrt_approx(fmaxf(xs0 + zs0 - 2.f * acc[mi][ni][0], 0.f)));
            float v01 = __expf(-0.1f * sqrt_approx(fmaxf(xs0 + zs1 - 2.f * acc[mi][ni][1], 0.f)));
            float v10 = __expf(-0.1f * sqrt_approx(fmaxf(xs1 + zs0 - 2.f * acc[mi][ni][2], 0.f)));
            float v11 = __expf(-0.1f * sqrt_approx(fmaxf(xs1 + zs1 - 2.f * acc[mi][ni][3], 0.f)));
            *reinterpret_cast<__half2*>(&smh[rl0 * EPS + cl]) = __floats2half2_rn(v00, v01);
            *reinterpret_cast<__half2*>(&smh[rl1 * EPS + cl]) = __floats2half2_rn(v10, v11);
        }
    }
    __syncthreads();
    // copy out: one fully contiguous 32KB tile (tiled kmat layout)
    const size_t tbase = ((size_t)blockIdx.y * 64 + blockIdx.x) * KTILE;
#pragma unroll
    for (int i = 0; i < 8; ++i) {
        int idx = i * 256 + tid;         // 0..2047 16B-chunks
        int row = idx >> 4;
        int off = idx & 15;
        uint4 v = *reinterpret_cast<const uint4*>(&smh[row * EPS + off * 8]);
        *reinterpret_cast<uint4*>(&g_kmath[tbase + (size_t)idx * 8]) = v;
    }
}

// ---------------------------------------------------------------------------
// G2: pred = kmat @ W, split-K=2. CTA 64 rows x 256 cols (all Y), K=4096/CTA.
// grid (2, 128) = 256 CTAs, 256 threads, occ 2. BK=64, 2-stage 1-sync.
// A read from TILED kmat: each slab = 64 rows x 128B at 256B stride, one
// 16KB-span per iteration (sector-dense, TLB-trivial).
// smem: A[2][64][72] half, B[2][256][72] half  (92160 B)
// 8 warps = 2(M) x 4(N); warp tile 32x64
// ---------------------------------------------------------------------------
#define TA2 (64 * SPH)
#define TB2 (256 * SPH)

__global__ __launch_bounds__(256, 2) void out_h_kernel(float* __restrict__ O) {
    extern __shared__ __half smh[];
    const uint32_t smb = smem_to_u32(smh);

    const int tid  = threadIdx.x;
    const int lane = tid & 31;
    const int warp = tid >> 5;
    const int quad = lane >> 2;
    const int tig  = lane & 3;
    const int lj   = lane >> 3;
    const int lr   = lane & 7;
    const int warpM = warp & 1;        // 32 rows
    const int warpN = warp >> 1;       // 64 cols
    const int rowBase = blockIdx.y * 64;
    const int kBase   = blockIdx.x * (MM / 2);   // split-K half

    // tiled kmat addressing
    const int tileN  = rowBase >> 7;          // 128-row tile index
    const int rowIn  = rowBase & 127;         // 0 or 64
    const __half* Bp = g_wth + kBase;

    float acc[2][8][4];
#pragma unroll
    for (int i = 0; i < 2; ++i)
#pragma unroll
        for (int j = 0; j < 8; ++j)
#pragma unroll
            for (int e = 0; e < 4; ++e) acc[i][j][e] = 0.f;

    auto load_slab = [&](int buf, int s) {
        const int kt = kBase + s * 64;
        const int tileM = kt >> 7;
        const int kIn   = kt & 127;           // 0 or 64
        const __half* Ap = g_kmath + ((size_t)tileN * 64 + tileM) * KTILE
                                   + (size_t)rowIn * 128 + kIn;
        const uint32_t dA = smb + (uint32_t)(buf * TA2) * 2;
        const uint32_t dB = smb + (uint32_t)(2 * TA2 + buf * TB2) * 2;
#pragma unroll
        for (int u = 0; u < 2; ++u) {  // A: 64 rows x 8 chunks = 512
            int idx = tid + u * 256;
            int r   = idx >> 3;
            int c8  = idx & 7;
            cpa16(dA + (uint32_t)(r * SPH + c8 * 8) * 2,
                  Ap + (size_t)r * 128 + c8 * 8);
        }
#pragma unroll
        for (int u = 0; u < 8; ++u) {  // B: 256 rows x 8 chunks = 2048
            int idx = tid + u * 256;
            int r   = idx >> 3;
            int c8  = idx & 7;
            cpa16(dB + (uint32_t)(r * SPH + c8 * 8) * 2,
                  Bp + (size_t)r * MM + (s * 64) + c8 * 8);
        }
        CPA_COMMIT();
    };

    auto compute = [&](int buf) {
        const uint32_t A = smb + (uint32_t)(buf * TA2) * 2;
        const uint32_t B = smb + (uint32_t)(2 * TA2 + buf * TB2) * 2;
#pragma unroll
        for (int kk = 0; kk < 64; kk += 16) {
            uint32_t afr[2][4], bfr[4][4];
#pragma unroll
            for (int mi = 0; mi < 2; ++mi) {
                int row = warpM * 32 + mi * 16 + (lj & 1) * 8 + lr;
                int col = kk + (lj >> 1) * 8;
                ldsm_x4(afr[mi], A + (uint32_t)(row * SPH + col) * 2);
            }
#pragma unroll
            for (int np = 0; np < 4; ++np) {
                int row = warpN * 64 + np * 16 + (lj >> 1) * 8 + lr;
                int col = kk + (lj & 1) * 8;
                ldsm_x4(bfr[np], B + (uint32_t)(row * SPH + col) * 2);
            }
#pragma unroll
            for (int mi = 0; mi < 2; ++mi)
#pragma unroll
                for (int np = 0; np < 4; ++np) {
                    mma_f16(acc[mi][np * 2 + 0], afr[mi], &bfr[np][0]);
                    mma_f16(acc[mi][np * 2 + 1], afr[mi], &bfr[np][2]);
                }
        }
    };

    const int S = (MM / 2) / 64;  // 64
    load_slab(0, 0);
#pragma unroll 1
    for (int s = 0; s < S; ++s) {
        CPA_WAIT(0);
        __syncthreads();
        if (s + 1 < S) load_slab((s + 1) & 1, s + 1);
        compute(s & 1);
    }

    // Epilogue: deterministic 2-way reduction (exactly 2 commutative addends)
#pragma unroll
    for (int mi = 0; mi < 2; ++mi) {
        int r0 = rowBase + warpM * 32 + mi * 16 + quad;
        int r1 = r0 + 8;
#pragma unroll
        for (int ni = 0; ni < 8; ++ni) {
            int c0 = warpN * 64 + ni * 8 + 2 * tig;
            redadd(&O[(size_t)r0 * YY + c0],     acc[mi][ni][0]);
            redadd(&O[(size_t)r0 * YY + c0 + 1], acc[mi][ni][1]);
            redadd(&O[(size_t)r1 * YY + c0],     acc[mi][ni][2]);
            redadd(&O[(size_t)r1 * YY + c0 + 1], acc[mi][ni][3]);
        }
    }
}

// ---------------------------------------------------------------------------
extern "C" void kernel_launch(void* const* d_in, const int* in_sizes, int n_in,
                              void* d_out, int out_size) {
    const float* X = (const float*)d_in[0];   // batch   [8192, 512]
    const float* Z = (const float*)d_in[1];   // centers [8192, 512]
    const float* W = (const float*)d_in[2];   // weight  [8192, 256]
    float* O = (float*)d_out;                 // pred    [8192, 256]

    const int smem1 = 6 * TSW;                  // 98304
    const int smem2 = (2 * TA2 + 2 * TB2) * 2;  // 92160
    cudaFuncSetAttribute(kmat_h_kernel, cudaFuncAttributeMaxDynamicSharedMemorySize, smem1);
    cudaFuncSetAttribute(out_h_kernel, cudaFuncAttributeMaxDynamicSharedMemorySize, smem2);

    __half* xh;  cudaGetSymbolAddress((void**)&xh, g_xh);
    __half* zh;  cudaGetSymbolAddress((void**)&zh, g_zh);
    float* xsq;  cudaGetSymbolAddress((void**)&xsq, g_xsq);
    float* zsq;  cudaGetSymbolAddress((void**)&zsq, g_zsq);

    prep_kernel<<<NN + MM, 128>>>(X, Z, xh, zh, xsq, zsq);
    wtrans_zero_kernel<<<dim3(YY / 32, MM / 32), dim3(32, 8)>>>(W, (float4*)O);

    kmat_h_kernel<<<dim3(MM / 128, NN / 128), 256, smem1>>>();
    out_h_kernel<<<dim3(2, NN / 64), 256, smem2>>>(O);
}

// round 16
// speedup vs baseline: 1.0166x; 1.0166x over previous
#include <cuda_runtime.h>
#include <cuda_fp16.h>
#include <math.h>
#include <stdint.h>

#define NN 8192
#define MM 8192
#define DD 512
#define YY 256

// Scratch (device globals -- no runtime allocation allowed)
__device__ __half g_kmath[(size_t)NN * (size_t)MM];  // 128 MB, row-major
__device__ __half g_xh[(size_t)NN * DD];             // 8 MB
__device__ __half g_zh[(size_t)MM * DD];             // 8 MB
__device__ __half g_wth[(size_t)YY * MM];            // W^T, 4 MB
__device__ float g_xsq[NN];
__device__ float g_zsq[MM];

// ---------------------------------------------------------------------------
__device__ __forceinline__ uint32_t smem_to_u32(const void* p) {
    uint32_t a;
    asm("{ .reg .u64 t; cvta.to.shared.u64 t, %1; cvt.u32.u64 %0, t; }"
        : "=r"(a) : "l"(p));
    return a;
}

__device__ __forceinline__ void mma_f16(float* c, const uint32_t* a, const uint32_t* b) {
    asm volatile(
        "mma.sync.aligned.m16n8k16.row.col.f32.f16.f16.f32 "
        "{%0,%1,%2,%3}, {%4,%5,%6,%7}, {%8,%9}, {%0,%1,%2,%3};\n"
        : "+f"(c[0]), "+f"(c[1]), "+f"(c[2]), "+f"(c[3])
        : "r"(a[0]), "r"(a[1]), "r"(a[2]), "r"(a[3]), "r"(b[0]), "r"(b[1]));
}

__device__ __forceinline__ void ldsm_x4(uint32_t* r, uint32_t addr) {
    asm volatile("ldmatrix.sync.aligned.m8n8.x4.shared.b16 {%0,%1,%2,%3}, [%4];"
                 : "=r"(r[0]), "=r"(r[1]), "=r"(r[2]), "=r"(r[3]) : "r"(addr));
}

__device__ __forceinline__ void cpa16(uint32_t dst, const void* src) {
    asm volatile("cp.async.cg.shared.global [%0], [%1], 16;" :: "r"(dst), "l"(src));
}
#define CPA_COMMIT() asm volatile("cp.async.commit_group;" ::: "memory")
#define CPA_WAIT(n)  asm volatile("cp.async.wait_group %0;" :: "n"(n) : "memory")

__device__ __forceinline__ float sqrt_approx(float x) {
    float r;
    asm("sqrt.approx.f32 %0, %1;" : "=f"(r) : "f"(x));
    return r;
}

__device__ __forceinline__ void redadd(float* p, float v) {
    asm volatile("red.global.add.f32 [%0], %1;" :: "l"(p), "f"(v) : "memory");
}

// SW128 swizzle for BK=64 fp16 rows (128 B/row): conflict-free cp.async + ldmatrix
__device__ __forceinline__ uint32_t swz(int row, int colh) {
    return (uint32_t)(row * 128 + ((colh * 2) ^ ((row & 7) * 16)));
}

// padded layout stride (halfs) for G2
#define SPH 72
// G1 epilogue staging stride (halfs)
#define EPS 136

// ---------------------------------------------------------------------------
// prep: one pass over X and Z: emit fp16 copy + row squared norm.
// ---------------------------------------------------------------------------
__global__ void prep_kernel(const float* __restrict__ X, const float* __restrict__ Z,
                            __half* __restrict__ xh, __half* __restrict__ zh,
                            float* __restrict__ xsq, float* __restrict__ zsq) {
    int b = blockIdx.x;
    const float* src;  __half* dst;  float* nrm;  int row;
    if (b < NN) { src = X; dst = xh; nrm = xsq; row = b; }
    else        { src = Z; dst = zh; nrm = zsq; row = b - NN; }
    const int t = threadIdx.x;
    float4 v = reinterpret_cast<const float4*>(src + (size_t)row * DD)[t];
    float s = v.x * v.x + v.y * v.y + v.z * v.z + v.w * v.w;
    __half2 h0 = __floats2half2_rn(v.x, v.y);
    __half2 h1 = __floats2half2_rn(v.z, v.w);
    uint2 packed;
    packed.x = *reinterpret_cast<uint32_t*>(&h0);
    packed.y = *reinterpret_cast<uint32_t*>(&h1);
    reinterpret_cast<uint2*>(dst + (size_t)row * DD)[t] = packed;
#pragma unroll
    for (int o = 16; o; o >>= 1) s += __shfl_down_sync(0xffffffffu, s, o);
    __shared__ float red[4];
    if ((t & 31) == 0) red[t >> 5] = s;
    __syncthreads();
    if (t == 0) nrm[row] = red[0] + red[1] + red[2] + red[3];
}

// W [8192, 256] -> g_wth [256, 8192] fp16; also zeroes O (same geometry).
__global__ void wtrans_zero_kernel(const float* __restrict__ W, float4* __restrict__ O) {
    __shared__ float t[32][33];
    int kb = blockIdx.y * 32, yb = blockIdx.x * 32;
    int tx = threadIdx.x, ty = threadIdx.y;  // 32 x 8
    int flat = ty * 32 + tx;
    size_t bid = (size_t)blockIdx.y * gridDim.x + blockIdx.x;   // 0..2047
    O[bid * 256 + flat] = make_float4(0.f, 0.f, 0.f, 0.f);
#pragma unroll
    for (int r = 0; r < 4; ++r)
        t[ty + r * 8][tx] = W[(size_t)(kb + ty + r * 8) * YY + yb + tx];
    __syncthreads();
#pragma unroll
    for (int r = 0; r < 4; ++r)
        g_wth[(size_t)(yb + ty + r * 8) * MM + kb + tx] =
            __float2half_rn(t[tx][ty + r * 8]);
}

// ---------------------------------------------------------------------------
// G1: S = X Z^T (CTA 128x128, BK=64, 3-stage 1-sync cp.async, SW128 smem)
// smem: 3 x (A + B) 16KB tiles = 98304 B -> occ 2
// 8 warps = 2(M) x 4(N); warp tile 64x32
// ---------------------------------------------------------------------------
#define TSW 16384

__global__ __launch_bounds__(256, 2) void kmat_h_kernel() {
    extern __shared__ __half smh[];
    const uint32_t smb = smem_to_u32(smh);

    const int tid  = threadIdx.x;
    const int lane = tid & 31;
    const int warp = tid >> 5;
    const int quad = lane >> 2;
    const int tig  = lane & 3;
    const int lj   = lane >> 3;
    const int lr   = lane & 7;
    const int warpM = warp & 1;
    const int warpN = warp >> 1;
    const int rowBase = blockIdx.y * 128;
    const int colBase = blockIdx.x * 128;

    const __half* Ap = g_xh + (size_t)rowBase * DD;
    const __half* Bp = g_zh + (size_t)colBase * DD;

    float acc[4][4][4];
#pragma unroll
    for (int i = 0; i < 4; ++i)
#pragma unroll
        for (int j = 0; j < 4; ++j)
#pragma unroll
            for (int e = 0; e < 4; ++e) acc[i][j][e] = 0.f;

    auto load_slab = [&](int buf, int s) {
        const int kt = s * 64;
        const uint32_t dA = smb + (uint32_t)buf * TSW;
        const uint32_t dB = smb + 3u * TSW + (uint32_t)buf * TSW;
#pragma unroll
        for (int u = 0; u < 4; ++u) {
            int idx = tid + u * 256;
            int r   = idx >> 3;
            int c8  = idx & 7;
            uint32_t so = swz(r, c8 * 8);
            cpa16(dA + so, Ap + (size_t)r * DD + kt + c8 * 8);
            cpa16(dB + so, Bp + (size_t)r * DD + kt + c8 * 8);
        }
        CPA_COMMIT();
    };

    auto compute = [&](int buf) {
        const uint32_t A = smb + (uint32_t)buf * TSW;
        const uint32_t B = smb + 3u * TSW + (uint32_t)buf * TSW;
#pragma unroll
        for (int kk = 0; kk < 64; kk += 16) {
            uint32_t afr[4][4], bfr[2][4];
#pragma unroll
            for (int mi = 0; mi < 4; ++mi) {
                int row = warpM * 64 + mi * 16 + (lj & 1) * 8 + lr;
                int col = kk + (lj >> 1) * 8;
                ldsm_x4(afr[mi], A + swz(row, col));
            }
#pragma unroll
            for (int np = 0; np < 2; ++np) {
                int row = warpN * 32 + np * 16 + (lj >> 1) * 8 + lr;
                int col = kk + (lj & 1) * 8;
                ldsm_x4(bfr[np], B + swz(row, col));
            }
#pragma unroll
            for (int mi = 0; mi < 4; ++mi)
#pragma unroll
                for (int np = 0; np < 2; ++np) {
                    mma_f16(acc[mi][np * 2 + 0], afr[mi], &bfr[np][0]);
                    mma_f16(acc[mi][np * 2 + 1], afr[mi], &bfr[np][2]);
                }
        }
    };

    const int S = DD / 64;  // 8
    load_slab(0, 0);
    load_slab(1, 1);
#pragma unroll 1
    for (int s = 0; s < S; ++s) {
        if (s + 1 < S) { CPA_WAIT(1); } else { CPA_WAIT(0); }
        __syncthreads();
        if (s + 2 < S) load_slab((s + 2) % 3, s + 2);
        compute(s % 3);
    }

    // Epilogue: laplacian -> fp16, staged through smem for coalesced stores
    __syncthreads();
#pragma unroll
    for (int mi = 0; mi < 4; ++mi) {
        int rl0 = warpM * 64 + mi * 16 + quad;
        int rl1 = rl0 + 8;
        float xs0 = __ldg(&g_xsq[rowBase + rl0]);
        float xs1 = __ldg(&g_xsq[rowBase + rl1]);
#pragma unroll
        for (int ni = 0; ni < 4; ++ni) {
            int cl = warpN * 32 + ni * 8 + 2 * tig;
            float zs0 = __ldg(&g_zsq[colBase + cl]);
            float zs1 = __ldg(&g_zsq[colBase + cl + 1]);
            float v00 = __expf(-0.1f * sqrt_approx(fmaxf(xs0 + zs0 - 2.f * acc[mi][ni][0], 0.f)));
            float v01 = __expf(-0.1f * sqrt_approx(fmaxf(xs0 + zs1 - 2.f * acc[mi][ni][1], 0.f)));
            float v10 = __expf(-0.1f * sqrt_approx(fmaxf(xs1 + zs0 - 2.f * acc[mi][ni][2], 0.f)));
            float v11 = __expf(-0.1f * sqrt_approx(fmaxf(xs1 + zs1 - 2.f * acc[mi][ni][3], 0.f)));
            *reinterpret_cast<__half2*>(&smh[rl0 * EPS + cl]) = __floats2half2_rn(v00, v01);
            *reinterpret_cast<__half2*>(&smh[rl1 * EPS + cl]) = __floats2half2_rn(v10, v11);
        }
    }
    __syncthreads();
#pragma unroll
    for (int i = 0; i < 8; ++i) {
        int ch  = i * 256 + tid;
        int row = ch >> 4;
        int off = ch & 15;
        uint4 v = *reinterpret_cast<const uint4*>(&smh[row * EPS + off * 8]);
        *reinterpret_cast<uint4*>(&g_kmath[(size_t)(rowBase + row) * MM + colBase + off * 8]) = v;
    }
}

// ---------------------------------------------------------------------------
// G2: pred = kmat @ W, split-K=2. CTA 256 rows x 128 y-cols, K=4096/CTA.
// grid (2 splitK, 32 n, 2 y) = 128 CTAs, 512 threads -> one balanced wave,
// 16 warps/SM. BK=64, 3-stage wait(1). chunks/MFLOP = 366 (G1 parity).
// smem: 3 x (A[256][72] + B[128][72]) half = 165888 B
// 16 warps = 4(M) x 4(N); warp tile 64x32 (G1's proven shape)
// Epilogue: red.global.add (2 addends/element).
// ---------------------------------------------------------------------------
#define TA2 (256 * SPH)
#define TB2 (128 * SPH)
#define ST2 (TA2 + TB2)   // one stage in halfs

__global__ __launch_bounds__(512, 1) void out_h_kernel(float* __restrict__ O) {
    extern __shared__ __half smh[];
    const uint32_t smb = smem_to_u32(smh);

    const int tid  = threadIdx.x;
    const int lane = tid & 31;
    const int warp = tid >> 5;        // 0..15
    const int quad = lane >> 2;
    const int tig  = lane & 3;
    const int lj   = lane >> 3;
    const int lr   = lane & 7;
    const int warpM = warp & 3;        // 64 rows each
    const int warpN = warp >> 2;       // 32 y-cols each
    const int rowBase = blockIdx.y * 256;
    const int yBase   = blockIdx.z * 128;
    const int kBase   = blockIdx.x * (MM / 2);   // split-K half

    const __half* Ap = g_kmath + (size_t)rowBase * MM + kBase;
    const __half* Bp = g_wth + (size_t)yBase * MM + kBase;

    float acc[4][4][4];
#pragma unroll
    for (int i = 0; i < 4; ++i)
#pragma unroll
        for (int j = 0; j < 4; ++j)
#pragma unroll
            for (int e = 0; e < 4; ++e) acc[i][j][e] = 0.f;

    auto load_slab = [&](int buf, int s) {
        const int kt = s * 64;
        const uint32_t dA = smb + (uint32_t)(buf * ST2) * 2;
        const uint32_t dB = smb + (uint32_t)(buf * ST2 + TA2) * 2;
#pragma unroll
        for (int u = 0; u < 4; ++u) {  // A: 256 rows x 8 chunks = 2048
            int idx = tid + u * 512;
            int r   = idx >> 3;
            int c8  = idx & 7;
            cpa16(dA + (uint32_t)(r * SPH + c8 * 8) * 2,
                  Ap + (size_t)r * MM + kt + c8 * 8);
        }
#pragma unroll
        for (int u = 0; u < 2; ++u) {  // B: 128 y-rows x 8 chunks = 1024
            int idx = tid + u * 512;
            int r   = idx >> 3;
            int c8  = idx & 7;
            cpa16(dB + (uint32_t)(r * SPH + c8 * 8) * 2,
                  Bp + (size_t)r * MM + kt + c8 * 8);
        }
        CPA_COMMIT();
    };

    auto compute = [&](int buf) {
        const uint32_t A = smb + (uint32_t)(buf * ST2) * 2;
        const uint32_t B = smb + (uint32_t)(buf * ST2 + TA2) * 2;
#pragma unroll
        for (int kk = 0; kk < 64; kk += 16) {
            uint32_t afr[4][4], bfr[2][4];
#pragma unroll
            for (int mi = 0; mi < 4; ++mi) {
                int row = warpM * 64 + mi * 16 + (lj & 1) * 8 + lr;
                int col = kk + (lj >> 1) * 8;
                ldsm_x4(afr[mi], A + (uint32_t)(row * SPH + col) * 2);
            }
#pragma unroll
            for (int np = 0; np < 2; ++np) {
                int row = warpN * 32 + np * 16 + (lj >> 1) * 8 + lr;
                int col = kk + (lj & 1) * 8;
                ldsm_x4(bfr[np], B + (uint32_t)(row * SPH + col) * 2);
            }
#pragma unroll
            for (int mi = 0; mi < 4; ++mi)
#pragma unroll
                for (int np = 0; np < 2; ++np) {
                    mma_f16(acc[mi][np * 2 + 0], afr[mi], &bfr[np][0]);
                    mma_f16(acc[mi][np * 2 + 1], afr[mi], &bfr[np][2]);
                }
        }
    };

    const int S = (MM / 2) / 64;  // 64
    load_slab(0, 0);
    load_slab(1, 1);
#pragma unroll 1
    for (int s = 0; s < S; ++s) {
        if (s + 1 < S) { CPA_WAIT(1); } else { CPA_WAIT(0); }
        __syncthreads();
        if (s + 2 < S) load_slab((s + 2) % 3, s + 2);
        compute(s % 3);
    }

    // Epilogue: deterministic 2-way reduction (exactly 2 commutative addends)
#pragma unroll
    for (int mi = 0; mi < 4; ++mi) {
        int r0 = rowBase + warpM * 64 + mi * 16 + quad;
        int r1 = r0 + 8;
#pragma unroll
        for (int ni = 0; ni < 4; ++ni) {
            int c0 = yBase + warpN * 32 + ni * 8 + 2 * tig;
            redadd(&O[(size_t)r0 * YY + c0],     acc[mi][ni][0]);
            redadd(&O[(size_t)r0 * YY + c0 + 1], acc[mi][ni][1]);
            redadd(&O[(size_t)r1 * YY + c0],     acc[mi][ni][2]);
            redadd(&O[(size_t)r1 * YY + c0 + 1], acc[mi][ni][3]);
        }
    }
}

// ---------------------------------------------------------------------------
extern "C" void kernel_launch(void* const* d_in, const int* in_sizes, int n_in,
                              void* d_out, int out_size) {
    const float* X = (const float*)d_in[0];   // batch   [8192, 512]
    const float* Z = (const float*)d_in[1];   // centers [8192, 512]
    const float* W = (const float*)d_in[2];   // weight  [8192, 256]
    float* O = (float*)d_out;                 // pred    [8192, 256]

    const int smem1 = 6 * TSW;       // 98304
    const int smem2 = 3 * ST2 * 2;   // 165888
    cudaFuncSetAttribute(kmat_h_kernel, cudaFuncAttributeMaxDynamicSharedMemorySize, smem1);
    cudaFuncSetAttribute(out_h_kernel, cudaFuncAttributeMaxDynamicSharedMemorySize, smem2);

    __half* xh;  cudaGetSymbolAddress((void**)&xh, g_xh);
    __half* zh;  cudaGetSymbolAddress((void**)&zh, g_zh);
    float* xsq;  cudaGetSymbolAddress((void**)&xsq, g_xsq);
    float* zsq;  cudaGetSymbolAddress((void**)&zsq, g_zsq);

    prep_kernel<<<NN + MM, 128>>>(X, Z, xh, zh, xsq, zsq);
    wtrans_zero_kernel<<<dim3(YY / 32, MM / 32), dim3(32, 8)>>>(W, (float4*)O);

    kmat_h_kernel<<<dim3(MM / 128, NN / 128), 256, smem1>>>();
    out_h_kernel<<<dim3(2, NN / 256, 2), 512, smem2>>>(O);
}

// round 17
// speedup vs baseline: 1.0212x; 1.0046x over previous
#include <cuda_runtime.h>
#include <cuda_fp16.h>
#include <math.h>
#include <stdint.h>

#define NN 8192
#define MM 8192
#define DD 512
#define YY 256

// Scratch (device globals -- no runtime allocation allowed)
__device__ __half g_kmath[(size_t)NN * (size_t)MM];  // 128 MB, row-major
__device__ __half g_xh[(size_t)NN * DD];             // 8 MB
__device__ __half g_zh[(size_t)MM * DD];             // 8 MB
__device__ __half g_wth[(size_t)YY * MM];            // W^T, 4 MB
__device__ float g_xsq[NN];
__device__ float g_zsq[MM];

// ---------------------------------------------------------------------------
__device__ __forceinline__ uint32_t smem_to_u32(const void* p) {
    uint32_t a;
    asm("{ .reg .u64 t; cvta.to.shared.u64 t, %1; cvt.u32.u64 %0, t; }"
        : "=r"(a) : "l"(p));
    return a;
}

__device__ __forceinline__ void mma_f16(float* c, const uint32_t* a, const uint32_t* b) {
    asm volatile(
        "mma.sync.aligned.m16n8k16.row.col.f32.f16.f16.f32 "
        "{%0,%1,%2,%3}, {%4,%5,%6,%7}, {%8,%9}, {%0,%1,%2,%3};\n"
        : "+f"(c[0]), "+f"(c[1]), "+f"(c[2]), "+f"(c[3])
        : "r"(a[0]), "r"(a[1]), "r"(a[2]), "r"(a[3]), "r"(b[0]), "r"(b[1]));
}

__device__ __forceinline__ void ldsm_x4(uint32_t* r, uint32_t addr) {
    asm volatile("ldmatrix.sync.aligned.m8n8.x4.shared.b16 {%0,%1,%2,%3}, [%4];"
                 : "=r"(r[0]), "=r"(r[1]), "=r"(r[2]), "=r"(r[3]) : "r"(addr));
}

__device__ __forceinline__ void cpa16(uint32_t dst, const void* src) {
    asm volatile("cp.async.cg.shared.global [%0], [%1], 16;" :: "r"(dst), "l"(src));
}
#define CPA_COMMIT() asm volatile("cp.async.commit_group;" ::: "memory")
#define CPA_WAIT(n)  asm volatile("cp.async.wait_group %0;" :: "n"(n) : "memory")

__device__ __forceinline__ float sqrt_approx(float x) {
    float r;
    asm("sqrt.approx.f32 %0, %1;" : "=f"(r) : "f"(x));
    return r;
}

__device__ __forceinline__ void redadd(float* p, float v) {
    asm volatile("red.global.add.f32 [%0], %1;" :: "l"(p), "f"(v) : "memory");
}

// SW128 swizzle for BK=64 fp16 rows (128 B/row): conflict-free cp.async + ldmatrix
__device__ __forceinline__ uint32_t swz(int row, int colh) {
    return (uint32_t)(row * 128 + ((colh * 2) ^ ((row & 7) * 16)));
}

// padded layout stride (halfs) for G2
#define SPH 72
// G1 epilogue staging stride (halfs)
#define EPS 136

// ---------------------------------------------------------------------------
// aux: ONE launch. blocks [0, NN+MM): per-row fp16 convert + squared norm.
//      blocks [NN+MM, NN+MM+2048): W transpose (32x32 tile) + O zeroing.
// 128 threads per block.
// ---------------------------------------------------------------------------
__global__ void aux_kernel(const float* __restrict__ X, const float* __restrict__ Z,
                           const float* __restrict__ W,
                           __half* __restrict__ xh, __half* __restrict__ zh,
                           float* __restrict__ xsq, float* __restrict__ zsq,
                           float4* __restrict__ O) {
    int b = blockIdx.x;
    const int t = threadIdx.x;
    if (b < NN + MM) {
        const float* src;  __half* dst;  float* nrm;  int row;
        if (b < NN) { src = X; dst = xh; nrm = xsq; row = b; }
        else        { src = Z; dst = zh; nrm = zsq; row = b - NN; }
        float4 v = reinterpret_cast<const float4*>(src + (size_t)row * DD)[t];
        float s = v.x * v.x + v.y * v.y + v.z * v.z + v.w * v.w;
        __half2 h0 = __floats2half2_rn(v.x, v.y);
        __half2 h1 = __floats2half2_rn(v.z, v.w);
        uint2 packed;
        packed.x = *reinterpret_cast<uint32_t*>(&h0);
        packed.y = *reinterpret_cast<uint32_t*>(&h1);
        reinterpret_cast<uint2*>(dst + (size_t)row * DD)[t] = packed;
#pragma unroll
        for (int o = 16; o; o >>= 1) s += __shfl_down_sync(0xffffffffu, s, o);
        __shared__ float red[4];
        if ((t & 31) == 0) red[t >> 5] = s;
        __syncthreads();
        if (t == 0) nrm[row] = red[0] + red[1] + red[2] + red[3];
    } else {
        // W transpose block: index wb in [0, 2048): wy = wb / 8 (k-tile), wx = wb % 8 (y-tile)
        int wb = b - (NN + MM);
        int kb = (wb >> 3) * 32;          // 256 k-tiles
        int yb = (wb & 7) * 32;           // 8 y-tiles
        int tx = t & 31;                  // 0..31
        int ty = t >> 5;                  // 0..3
        // zero O: 2048 blocks x 256 float4 = 2M float4; 128 threads -> 2 each
        size_t obase = (size_t)wb * 256;
        O[obase + t]       = make_float4(0.f, 0.f, 0.f, 0.f);
        O[obase + t + 128] = make_float4(0.f, 0.f, 0.f, 0.f);
        __shared__ float tt[32][33];
#pragma unroll
        for (int r = 0; r < 8; ++r)
            tt[ty + r * 4][tx] = W[(size_t)(kb + ty + r * 4) * YY + yb + tx];
        __syncthreads();
#pragma unroll
        for (int r = 0; r < 8; ++r)
            g_wth[(size_t)(yb + ty + r * 4) * MM + kb + tx] =
                __float2half_rn(tt[tx][ty + r * 4]);
    }
}

// ---------------------------------------------------------------------------
// G1: S = X Z^T (CTA 128x128, BK=64, 3-stage 1-sync cp.async, SW128 smem)
// smem: 3 x (A + B) 16KB tiles = 98304 B -> occ 2
// 8 warps = 2(M) x 4(N); warp tile 64x32
// ---------------------------------------------------------------------------
#define TSW 16384

__global__ __launch_bounds__(256, 2) void kmat_h_kernel() {
    extern __shared__ __half smh[];
    const uint32_t smb = smem_to_u32(smh);

    const int tid  = threadIdx.x;
    const int lane = tid & 31;
    const int warp = tid >> 5;
    const int quad = lane >> 2;
    const int tig  = lane & 3;
    const int lj   = lane >> 3;
    const int lr   = lane & 7;
    const int warpM = warp & 1;
    const int warpN = warp >> 1;
    const int rowBase = blockIdx.y * 128;
    const int colBase = blockIdx.x * 128;

    const __half* Ap = g_xh + (size_t)rowBase * DD;
    const __half* Bp = g_zh + (size_t)colBase * DD;

    float acc[4][4][4];
#pragma unroll
    for (int i = 0; i < 4; ++i)
#pragma unroll
        for (int j = 0; j < 4; ++j)
#pragma unroll
            for (int e = 0; e < 4; ++e) acc[i][j][e] = 0.f;

    auto load_slab = [&](int buf, int s) {
        const int kt = s * 64;
        const uint32_t dA = smb + (uint32_t)buf * TSW;
        const uint32_t dB = smb + 3u * TSW + (uint32_t)buf * TSW;
#pragma unroll
        for (int u = 0; u < 4; ++u) {
            int idx = tid + u * 256;
            int r   = idx >> 3;
            int c8  = idx & 7;
            uint32_t so = swz(r, c8 * 8);
            cpa16(dA + so, Ap + (size_t)r * DD + kt + c8 * 8);
            cpa16(dB + so, Bp + (size_t)r * DD + kt + c8 * 8);
        }
        CPA_COMMIT();
    };

    auto compute = [&](int buf) {
        const uint32_t A = smb + (uint32_t)buf * TSW;
        const uint32_t B = smb + 3u * TSW + (uint32_t)buf * TSW;
#pragma unroll
        for (int kk = 0; kk < 64; kk += 16) {
            uint32_t afr[4][4], bfr[2][4];
#pragma unroll
            for (int mi = 0; mi < 4; ++mi) {
                int row = warpM * 64 + mi * 16 + (lj & 1) * 8 + lr;
                int col = kk + (lj >> 1) * 8;
                ldsm_x4(afr[mi], A + swz(row, col));
            }
#pragma unroll
            for (int np = 0; np < 2; ++np) {
                int row = warpN * 32 + np * 16 + (lj >> 1) * 8 + lr;
                int col = kk + (lj & 1) * 8;
                ldsm_x4(bfr[np], B + swz(row, col));
            }
#pragma unroll
            for (int mi = 0; mi < 4; ++mi)
#pragma unroll
                for (int np = 0; np < 2; ++np) {
                    mma_f16(acc[mi][np * 2 + 0], afr[mi], &bfr[np][0]);
                    mma_f16(acc[mi][np * 2 + 1], afr[mi], &bfr[np][2]);
                }
        }
    };

    const int S = DD / 64;  // 8
    load_slab(0, 0);
    load_slab(1, 1);
#pragma unroll 1
    for (int s = 0; s < S; ++s) {
        if (s + 1 < S) { CPA_WAIT(1); } else { CPA_WAIT(0); }
        __syncthreads();
        if (s + 2 < S) load_slab((s + 2) % 3, s + 2);
        compute(s % 3);
    }

    // Epilogue: laplacian -> fp16, staged through smem for coalesced stores
    __syncthreads();
#pragma unroll
    for (int mi = 0; mi < 4; ++mi) {
        int rl0 = warpM * 64 + mi * 16 + quad;
        int rl1 = rl0 + 8;
        float xs0 = __ldg(&g_xsq[rowBase + rl0]);
        float xs1 = __ldg(&g_xsq[rowBase + rl1]);
#pragma unroll
        for (int ni = 0; ni < 4; ++ni) {
            int cl = warpN * 32 + ni * 8 + 2 * tig;
            float zs0 = __ldg(&g_zsq[colBase + cl]);
            float zs1 = __ldg(&g_zsq[colBase + cl + 1]);
            float v00 = __expf(-0.1f * sqrt_approx(fmaxf(xs0 + zs0 - 2.f * acc[mi][ni][0], 0.f)));
            float v01 = __expf(-0.1f * sqrt_approx(fmaxf(xs0 + zs1 - 2.f * acc[mi][ni][1], 0.f)));
            float v10 = __expf(-0.1f * sqrt_approx(fmaxf(xs1 + zs0 - 2.f * acc[mi][ni][2], 0.f)));
            float v11 = __expf(-0.1f * sqrt_approx(fmaxf(xs1 + zs1 - 2.f * acc[mi][ni][3], 0.f)));
            *reinterpret_cast<__half2*>(&smh[rl0 * EPS + cl]) = __floats2half2_rn(v00, v01);
            *reinterpret_cast<__half2*>(&smh[rl1 * EPS + cl]) = __floats2half2_rn(v10, v11);
        }
    }
    __syncthreads();
#pragma unroll
    for (int i = 0; i < 8; ++i) {
        int ch  = i * 256 + tid;
        int row = ch >> 4;
        int off = ch & 15;
        uint4 v = *reinterpret_cast<const uint4*>(&smh[row * EPS + off * 8]);
        *reinterpret_cast<uint4*>(&g_kmath[(size_t)(rowBase + row) * MM + colBase + off * 8]) = v;
    }
}

// ---------------------------------------------------------------------------
// G2: pred = kmat @ W, split-K=2. CTA 256 rows x 128 y-cols, K=4096/CTA.
// grid (2 splitK, 32 n, 2 y) = 128 CTAs, 512 threads, one balanced wave.
// BK=64, 3-stage wait(1). ROW ORDER REVERSED: first CTAs read the
// last-written (L2-resident) kmat rows, chasing the eviction frontier.
// smem: 3 x (A[256][72] + B[128][72]) half = 165888 B
// 16 warps = 4(M) x 4(N); warp tile 64x32
// Epilogue: red.global.add (2 addends/element).
// ---------------------------------------------------------------------------
#define TA2 (256 * SPH)
#define TB2 (128 * SPH)
#define ST2 (TA2 + TB2)   // one stage in halfs

__global__ __launch_bounds__(512, 1) void out_h_kernel(float* __restrict__ O) {
    extern __shared__ __half smh[];
    const uint32_t smb = smem_to_u32(smh);

    const int tid  = threadIdx.x;
    const int lane = tid & 31;
    const int warp = tid >> 5;        // 0..15
    const int quad = lane >> 2;
    const int tig  = lane & 3;
    const int lj   = lane >> 3;
    const int lr   = lane & 7;
    const int warpM = warp & 3;        // 64 rows each
    const int warpN = warp >> 2;       // 32 y-cols each
    const int rowBase = (int)(gridDim.y - 1 - blockIdx.y) * 256;   // REVERSED
    const int yBase   = blockIdx.z * 128;
    const int kBase   = blockIdx.x * (MM / 2);   // split-K half

    const __half* Ap = g_kmath + (size_t)rowBase * MM + kBase;
    const __half* Bp = g_wth + (size_t)yBase * MM + kBase;

    float acc[4][4][4];
#pragma unroll
    for (int i = 0; i < 4; ++i)
#pragma unroll
        for (int j = 0; j < 4; ++j)
#pragma unroll
            for (int e = 0; e < 4; ++e) acc[i][j][e] = 0.f;

    auto load_slab = [&](int buf, int s) {
        const int kt = s * 64;
        const uint32_t dA = smb + (uint32_t)(buf * ST2) * 2;
        const uint32_t dB = smb + (uint32_t)(buf * ST2 + TA2) * 2;
#pragma unroll
        for (int u = 0; u < 4; ++u) {  // A: 256 rows x 8 chunks = 2048
            int idx = tid + u * 512;
            int r   = idx >> 3;
            int c8  = idx & 7;
            cpa16(dA + (uint32_t)(r * SPH + c8 * 8) * 2,
                  Ap + (size_t)r * MM + kt + c8 * 8);
        }
#pragma unroll
        for (int u = 0; u < 2; ++u) {  // B: 128 y-rows x 8 chunks = 1024
            int idx = tid + u * 512;
            int r   = idx >> 3;
            int c8  = idx & 7;
            cpa16(dB + (uint32_t)(r * SPH + c8 * 8) * 2,
                  Bp + (size_t)r * MM + kt + c8 * 8);
        }
        CPA_COMMIT();
    };

    auto compute = [&](int buf) {
        const uint32_t A = smb + (uint32_t)(buf * ST2) * 2;
        const uint32_t B = smb + (uint32_t)(buf * ST2 + TA2) * 2;
#pragma unroll
        for (int kk = 0; kk < 64; kk += 16) {
            uint32_t afr[4][4], bfr[2][4];
#pragma unroll
            for (int mi = 0; mi < 4; ++mi) {
                int row = warpM * 64 + mi * 16 + (lj & 1) * 8 + lr;
                int col = kk + (lj >> 1) * 8;
                ldsm_x4(afr[mi], A + (uint32_t)(row * SPH + col) * 2);
            }
#pragma unroll
            for (int np = 0; np < 2; ++np) {
                int row = warpN * 32 + np * 16 + (lj >> 1) * 8 + lr;
                int col = kk + (lj & 1) * 8;
                ldsm_x4(bfr[np], B + (uint32_t)(row * SPH + col) * 2);
            }
#pragma unroll
            for (int mi = 0; mi < 4; ++mi)
#pragma unroll
                for (int np = 0; np < 2; ++np) {
                    mma_f16(acc[mi][np * 2 + 0], afr[mi], &bfr[np][0]);
                    mma_f16(acc[mi][np * 2 + 1], afr[mi], &bfr[np][2]);
                }
        }
    };

    const int S = (MM / 2) / 64;  // 64
    load_slab(0, 0);
    load_slab(1, 1);
#pragma unroll 1
    for (int s = 0; s < S; ++s) {
        if (s + 1 < S) { CPA_WAIT(1); } else { CPA_WAIT(0); }
        __syncthreads();
        if (s + 2 < S) load_slab((s + 2) % 3, s + 2);
        compute(s % 3);
    }

    // Epilogue: deterministic 2-way reduction (exactly 2 commutative addends)
#pragma unroll
    for (int mi = 0; mi < 4; ++mi) {
        int r0 = rowBase + warpM * 64 + mi * 16 + quad;
        int r1 = r0 + 8;
#pragma unroll
        for (int ni = 0; ni < 4; ++ni) {
            int c0 = yBase + warpN * 32 + ni * 8 + 2 * tig;
            redadd(&O[(size_t)r0 * YY + c0],     acc[mi][ni][0]);
            redadd(&O[(size_t)r0 * YY + c0 + 1], acc[mi][ni][1]);
            redadd(&O[(size_t)r1 * YY + c0],     acc[mi][ni][2]);
            redadd(&O[(size_t)r1 * YY + c0 + 1], acc[mi][ni][3]);
        }
    }
}

// ---------------------------------------------------------------------------
extern "C" void kernel_launch(void* const* d_in, const int* in_sizes, int n_in,
                              void* d_out, int out_size) {
    const float* X = (const float*)d_in[0];   // batch   [8192, 512]
    const float* Z = (const float*)d_in[1];   // centers [8192, 512]
    const float* W = (const float*)d_in[2];   // weight  [8192, 256]
    float* O = (float*)d_out;                 // pred    [8192, 256]

    const int smem1 = 6 * TSW;       // 98304
    const int smem2 = 3 * ST2 * 2;   // 165888
    cudaFuncSetAttribute(kmat_h_kernel, cudaFuncAttributeMaxDynamicSharedMemorySize, smem1);
    cudaFuncSetAttribute(out_h_kernel, cudaFuncAttributeMaxDynamicSharedMemorySize, smem2);

    __half* xh;  cudaGetSymbolAddress((void**)&xh, g_xh);
    __half* zh;  cudaGetSymbolAddress((void**)&zh, g_zh);
    float* xsq;  cudaGetSymbolAddress((void**)&xsq, g_xsq);
    float* zsq;  cudaGetSymbolAddress((void**)&zsq, g_zsq);

    aux_kernel<<<NN + MM + 2048, 128>>>(X, Z, W, xh, zh, xsq, zsq, (float4*)O);
    kmat_h_kernel<<<dim3(MM / 128, NN / 128), 256, smem1>>>();
    out_h_kernel<<<dim3(2, NN / 256, 2), 512, smem2>>>(O);
}